// round 13
// baseline (speedup 1.0000x reference)
#include <cuda_runtime.h>
#include <cstdint>

// FlowNetC correlation: B=4, C=128, H=W=96, md=20, stride2=2, K=1, S1=1.
// out[b, iy*21+ix, y, x] = (1/128)*sum_c in1[b,c,y,x]*in2[b,c,y+dy,x+dx]
// dy=(iy-10)*2, dx=(ix-10)*2, zero outside [0,96).
//
// Thread tile: 7 dx x 12 x (42 f32x2 accs). Warp mapping (dxg,dyg,xg) +
// KROW == 2 mod 32 words -> k LDS.64 at the 2-wavefront floor, q LDS.128 1 wf.
// Double-buffered smem chunks with register prefetch: 1 sync/chunk, LDG
// latency hidden under compute.

#define ND 21
#define NDD 441
#define CH 128
#define HH 96
#define WW 96
#define DYG 7
#define CCK 8
#define NCHUNK 16
#define QSTP 100
#define KX 144                // K row: [0..19]=0, [20..115]=data, rest 0
#define KROW 1154             // 8*KX + 2 ; == 2 mod 32 words (bank-class split)
#define QB0 0
#define QB1 800
#define KB0 1600              // == 0 mod 32 words
#define KBUF 8096             // 7*KROW=8078, padded to mod-32
#define KB1 (KB0 + KBUF)
#define SMEMF (KB1 + KBUF)    // 17792 floats
#define SMEMB (SMEMF*4)       // 71168 B -> 2 blocks/SM
#define NT 192
#define NACT 168              // 3 dxg * 7 dyg * 8 xg

typedef unsigned long long u64;

__device__ __forceinline__ u64 ffma2(u64 a, u64 b, u64 c) {
    u64 d;
    asm("fma.rn.f32x2 %0, %1, %2, %3;" : "=l"(d) : "l"(a), "l"(b), "l"(c));
    return d;
}

__global__ void __launch_bounds__(NT, 2)
corr_kernel(const float* __restrict__ in1, const float* __restrict__ in2,
            float* __restrict__ out)
{
    extern __shared__ float smem[];
    const int y   = blockIdx.x;
    const int b   = blockIdx.y;
    const int p   = blockIdx.z;        // dy rows p*7 .. p*7+6
    const int tid = threadIdx.x;

    // Zero both K buffers once (pads must stay zero; interior rewritten)
    for (int i = tid; i < (SMEMF - KB0) / 4; i += NT)
        *(float4*)(smem + KB0 + 4 * i) = make_float4(0.f, 0.f, 0.f, 0.f);

    // Loader coords: each thread owns (channel lc, quad lx) for Q and all 7 K rows
    const int lc = tid / 24;
    const int lx = tid - lc * 24;

#define LDG_Q(reg, CC) \
    reg = *(const float4*)(in1 + (((size_t)b*CH + (CC)*CCK + lc)*HH + y)*WW + 4*lx)
#define LDG_K(reg, CC, J) do { \
    int yy_ = y + (p*DYG + (J) - 10)*2; \
    reg = make_float4(0.f,0.f,0.f,0.f); \
    if ((unsigned)yy_ < HH) \
        reg = *(const float4*)(in2 + (((size_t)b*CH + (CC)*CCK + lc)*HH + yy_)*WW + 4*lx); \
    } while (0)
#define STS_Q(reg, QB) *(float4*)(smem + (QB) + lc*QSTP + 4*lx) = reg
#define STS_K(reg, KB, J) do { \
    float* d_ = smem + (KB) + (J)*KROW + lc*KX + 20 + 4*lx; \
    *(float2*)d_       = make_float2(reg.x, reg.y); \
    *(float2*)(d_ + 2) = make_float2(reg.z, reg.w); \
    } while (0)

    // ---- chunk 0 into buffer 0 ----
    {
        float4 t;
        LDG_Q(t, 0); STS_Q(t, QB0);
        #pragma unroll
        for (int j = 0; j < 7; ++j) { LDG_K(t, 0, j); STS_K(t, KB0, j); }
    }

    // Tile mapping: dxg outer, dyg mid, xg inner (warps span 1 dxg x 4 dyg x 8 xg)
    const bool active = tid < NACT;
    int dxg = 0, dyg = 0, xg = 0;
    if (active) {
        dxg = tid / 56;
        int r = tid - dxg * 56;
        dyg = r / 8;
        xg  = r - dyg * 8;
    }
    const int x0   = 12 * xg;
    const int koff = 12 * xg + 14 * dxg;   // logical window base (even)

    u64 acc2[7][6];
    #pragma unroll
    for (int j = 0; j < 7; ++j)
        #pragma unroll
        for (int n = 0; n < 6; ++n) acc2[j][n] = 0ull;

    __syncthreads();

#define COMPUTE_HALF(QB, KB, C0) do { \
    if (active) { \
        _Pragma("unroll 1") \
        for (int c = (C0); c < (C0) + 4; ++c) { \
            const float* qp_ = smem + (QB) + c * QSTP + x0; \
            const float* kp_ = smem + (KB) + dyg * KROW + c * KX + koff; \
            u64 q2_[6], k2_[12]; \
            _Pragma("unroll") \
            for (int t = 0; t < 3; ++t) { \
                ulonglong2 v_ = *(const ulonglong2*)(qp_ + 4 * t); \
                q2_[2*t] = v_.x; q2_[2*t+1] = v_.y; \
            } \
            _Pragma("unroll") \
            for (int t = 0; t < 12; ++t) k2_[t] = *(const u64*)(kp_ + 2 * t); \
            _Pragma("unroll") \
            for (int j = 0; j < 7; ++j) \
                _Pragma("unroll") \
                for (int n = 0; n < 6; ++n) \
                    acc2[j][n] = ffma2(q2_[n], k2_[n + j], acc2[j][n]); \
        } \
    } } while (0)

    for (int cc = 0; cc < NCHUNK; ++cc) {
        const int qb = (cc & 1) ? QB1 : QB0;
        const int kb = (cc & 1) ? KB1 : KB0;
        const int qn = (cc & 1) ? QB0 : QB1;
        const int kn = (cc & 1) ? KB0 : KB1;
        const bool pf = (cc + 1 < NCHUNK);

        float4 a0, a1, a2, a3;
        if (pf) { LDG_Q(a0, cc + 1); LDG_K(a1, cc + 1, 0);
                  LDG_K(a2, cc + 1, 1); LDG_K(a3, cc + 1, 2); }
        COMPUTE_HALF(qb, kb, 0);
        if (pf) { STS_Q(a0, qn); STS_K(a1, kn, 0);
                  STS_K(a2, kn, 1); STS_K(a3, kn, 2); }

        float4 b0, b1, b2, b3;
        if (pf) { LDG_K(b0, cc + 1, 3); LDG_K(b1, cc + 1, 4);
                  LDG_K(b2, cc + 1, 5); LDG_K(b3, cc + 1, 6); }
        COMPUTE_HALF(qb, kb, 4);
        if (pf) { STS_K(b0, kn, 3); STS_K(b1, kn, 4);
                  STS_K(b2, kn, 5); STS_K(b3, kn, 6); }

        __syncthreads();
    }

    if (active) {
        const int diy = p * DYG + dyg;
        const float s = 1.0f / 128.0f;
        #pragma unroll
        for (int j = 0; j < 7; ++j) {
            int d = diy * ND + dxg * 7 + j;
            float* o = out + (((size_t)b * NDD + d) * HH + y) * WW + x0;
            #pragma unroll
            for (int m = 0; m < 3; ++m) {
                float2 a0 = *(float2*)&acc2[j][2 * m];
                float2 a1 = *(float2*)&acc2[j][2 * m + 1];
                *(float4*)(o + 4 * m) =
                    make_float4(a0.x * s, a0.y * s, a1.x * s, a1.y * s);
            }
        }
    }
}

extern "C" void kernel_launch(void* const* d_in, const int* in_sizes, int n_in,
                              void* d_out, int out_size)
{
    const float* in1 = (const float*)d_in[0];
    const float* in2 = (const float*)d_in[1];
    float* out = (float*)d_out;

    cudaFuncSetAttribute(corr_kernel,
                         cudaFuncAttributeMaxDynamicSharedMemorySize, SMEMB);
    corr_kernel<<<dim3(HH, 4, 3), NT, SMEMB>>>(in1, in2, out);
}